// round 17
// baseline (speedup 1.0000x reference)
#include <cuda_runtime.h>
#include <cuda_fp16.h>
#include <cstdint>

// Problem constants
#define BB 4
#define SS 2048
#define HH 2048
#define NH 16
#define HD 128
#define MM (BB*SS)            // 8192 rows

// Fragment-packed FP16 operand layouts (mma m16n8k16):
//  A-pack 16B/lane per m16xk16 block: u0={A[g][2t],A[g][2t+1]}, u1={A[g+8][..]},
//    u2={A[g][2t+8],[+9]}, u3={A[g+8][2t+8],[+9]}
//  B-pack 16B/lane per n16xk16 block: u0={W[g][2t],[+1]}, u1={W[g][2t+8],[+9]},
//    u2={W[g+8][2t],[+1]}, u3={W[g+8][2t+8],[+9]}
// g_x / g_o: A-pack [mt=64][ks=32][m16=8][k16=4][lane]      (1024 uint4 / slab)
// g_w[z]:    B-pack [nt=16][ks=32][n16=8][k16=4][lane]
// g_q per (b,h): [qt64=32][m16=4][k16=8][lane]              (1024 uint4 / tile)
// g_k per (b,h): [kt=32][n16=4][k16=8][lane]
// g_v per (b,h): [kt=32][n16=8][k16=4][lane]  (n=headdim, k=seq)
__device__ uint32_t g_q[BB*NH*SS*HD/2];
__device__ uint32_t g_k[BB*NH*SS*HD/2];
__device__ uint32_t g_v[BB*NH*SS*HD/2];
__device__ uint32_t g_o[MM*HH/2];
__device__ uint32_t g_x[MM*HH/2];
__device__ uint32_t g_w[4][HH*HH/2];

#define WSTRIDE_U4 (HH*HH/8)   // 524288 uint4 per packed weight

__device__ __forceinline__ uint32_t pk2(float lo, float hi) {
    uint32_t u; asm("cvt.rn.f16x2.f32 %0, %1, %2;" : "=r"(u) : "f"(hi), "f"(lo)); return u;
}

__device__ __forceinline__ void mma_fp16(float c[4], const uint32_t a[4], const uint32_t b[2]) {
    asm volatile(
        "mma.sync.aligned.m16n8k16.row.col.f32.f16.f16.f32 "
        "{%0,%1,%2,%3},{%4,%5,%6,%7},{%8,%9},{%0,%1,%2,%3};"
        : "+f"(c[0]), "+f"(c[1]), "+f"(c[2]), "+f"(c[3])
        : "r"(a[0]), "r"(a[1]), "r"(a[2]), "r"(a[3]), "r"(b[0]), "r"(b[1]));
}

__device__ __forceinline__ void cpa16(uint32_t s, const void* g) {
    asm volatile("cp.async.cg.shared.global [%0], [%1], 16;\n" :: "r"(s), "l"(g));
}
__device__ __forceinline__ void cpa_commit() {
    asm volatile("cp.async.commit_group;\n" ::: "memory");
}
template<int N> __device__ __forceinline__ void cpa_wait() {
    asm volatile("cp.async.wait_group %0;\n" :: "n"(N) : "memory");
}

// ============================================================================
// Smem-staged packing: block = one (tile, ks) slab of 128 rows x 64 cols.
// Coalesced float4 row reads -> f16x2 pairs in padded smem -> linear u4 writes.
// ============================================================================
__global__ void pack_a_kernel(const float* __restrict__ in, uint4* __restrict__ out) {
    __shared__ uint32_t sp[128][33];     // f16x2 pairs (col-pair index 0..31)
    const int mt = blockIdx.x, ks = blockIdx.y;
    const int tid = threadIdx.x;
    const float* base = in + ((size_t)mt * 128) * HH + ks * 64;
    #pragma unroll
    for (int i = 0; i < 8; i++) {
        int f = i * 256 + tid;           // float4 index: 128 rows x 16
        int r = f >> 4, c4 = f & 15;
        float4 v = *reinterpret_cast<const float4*>(base + (size_t)r * HH + c4 * 4);
        sp[r][c4 * 2]     = pk2(v.x, v.y);
        sp[r][c4 * 2 + 1] = pk2(v.z, v.w);
    }
    __syncthreads();
    uint4* dst = out + ((size_t)(mt * 32 + ks)) * 1024;
    #pragma unroll
    for (int i = 0; i < 4; i++) {
        int o = i * 256 + tid;           // local u4 index
        int lane = o & 31, k16 = (o >> 5) & 3, m16 = o >> 7;
        int g = lane >> 2, t = lane & 3;
        int r = m16 * 16 + g;
        uint4 v;
        v.x = sp[r][k16 * 8 + t];
        v.y = sp[r + 8][k16 * 8 + t];
        v.z = sp[r][k16 * 8 + t + 4];
        v.w = sp[r + 8][k16 * 8 + t + 4];
        dst[o] = v;
    }
}

__global__ void pack_b_kernel(const float* __restrict__ w0, const float* __restrict__ w1,
                              const float* __restrict__ w2, const float* __restrict__ w3,
                              uint4* __restrict__ out) {
    __shared__ uint32_t sp[128][33];
    const int nt = blockIdx.x, ks = blockIdx.y, z = blockIdx.z;
    const int tid = threadIdx.x;
    const float* in = (z == 0) ? w0 : (z == 1) ? w1 : (z == 2) ? w2 : w3;
    const float* base = in + ((size_t)nt * 128) * HH + ks * 64;
    #pragma unroll
    for (int i = 0; i < 8; i++) {
        int f = i * 256 + tid;
        int r = f >> 4, c4 = f & 15;
        float4 v = *reinterpret_cast<const float4*>(base + (size_t)r * HH + c4 * 4);
        sp[r][c4 * 2]     = pk2(v.x, v.y);
        sp[r][c4 * 2 + 1] = pk2(v.z, v.w);
    }
    __syncthreads();
    uint4* dst = out + (size_t)z * WSTRIDE_U4 + ((size_t)(nt * 32 + ks)) * 1024;
    #pragma unroll
    for (int i = 0; i < 4; i++) {
        int o = i * 256 + tid;
        int lane = o & 31, k16 = (o >> 5) & 3, n16 = o >> 7;
        int g = lane >> 2, t = lane & 3;
        int r = n16 * 16 + g;
        uint4 v;
        v.x = sp[r][k16 * 8 + t];
        v.y = sp[r][k16 * 8 + t + 4];
        v.z = sp[r + 8][k16 * 8 + t];
        v.w = sp[r + 8][k16 * 8 + t + 4];
        dst[o] = v;
    }
}

// ============================================================================
// FP16 GEMM: C = A * W^T  (m16n8k16, CTA 128x128, BK=64/stage, 3-stage
// cp.async, 256 thr, 2 CTAs/SM).  qkv_mode=1: scatter to packed Q/K/V.
// ============================================================================
#define GSTG 3
#define STG_U4 1024                        // uint4 per A (or B) stage = 16KB
#define GEMM_SMEM (GSTG * 2 * STG_U4 * 16) // 98304 bytes

__global__ void __launch_bounds__(256, 2) gemm_fp16_kernel(
    const uint4* __restrict__ Apack, const uint4* __restrict__ Wpack,
    uint32_t* __restrict__ Cq, uint32_t* __restrict__ Ck, uint32_t* __restrict__ Cv,
    float* __restrict__ Cf, int qkv_mode)
{
    extern __shared__ uint4 sm4[];
    uint4* As = sm4;                       // [GSTG][STG_U4]
    uint4* Bs = sm4 + GSTG * STG_U4;

    const int tid  = threadIdx.x;
    const int lane = tid & 31;
    const int warp = tid >> 5;
    const int g = lane >> 2, t = lane & 3;
    const int wm = warp & 3, wn = warp >> 2;   // warp tile 32x64
    const int mt = blockIdx.y;
    const int nt = blockIdx.x;
    const int z  = blockIdx.z;

    const uint4* Ab = Apack + ((size_t)mt * 32) * STG_U4;
    const uint4* Bb = Wpack + (size_t)z * WSTRIDE_U4 + ((size_t)nt * 32) * STG_U4;

    const uint32_t sA = (uint32_t)__cvta_generic_to_shared(As);
    const uint32_t sB = (uint32_t)__cvta_generic_to_shared(Bs);

    auto load_stage = [&](int s, int ks) {
        uint32_t bA = sA + (uint32_t)(s * STG_U4) * 16u;
        uint32_t bB = sB + (uint32_t)(s * STG_U4) * 16u;
        const uint4* pA = Ab + (size_t)ks * STG_U4;
        const uint4* pB = Bb + (size_t)ks * STG_U4;
        #pragma unroll
        for (int i = 0; i < 4; i++) {
            int off = i * 256 + tid;
            cpa16(bA + (uint32_t)off * 16u, pA + off);
            cpa16(bB + (uint32_t)off * 16u, pB + off);
        }
        cpa_commit();
    };

    float acc[2][8][4];
    #pragma unroll
    for (int mi = 0; mi < 2; mi++)
        #pragma unroll
        for (int ni = 0; ni < 8; ni++)
            #pragma unroll
            for (int j = 0; j < 4; j++) acc[mi][ni][j] = 0.f;

    load_stage(0, 0);
    load_stage(1, 1);
    cpa_wait<1>();
    __syncthreads();

    const int nk = 32;      // 2048 / 64
    #pragma unroll 1
    for (int kt = 0; kt < nk; kt++) {
        const int cur = kt % GSTG;
        if (kt + 2 < nk) load_stage((kt + 2) % GSTG, kt + 2);
        else             cpa_commit();

        const uint4* Ac = As + cur * STG_U4;
        const uint4* Bc = Bs + cur * STG_U4;

        #pragma unroll
        for (int kk = 0; kk < 4; kk++) {
            uint4 av0 = Ac[((wm * 2 + 0) * 4 + kk) * 32 + lane];
            uint4 av1 = Ac[((wm * 2 + 1) * 4 + kk) * 32 + lane];
            uint32_t a0[4] = {av0.x, av0.y, av0.z, av0.w};
            uint32_t a1[4] = {av1.x, av1.y, av1.z, av1.w};
            #pragma unroll
            for (int j = 0; j < 4; j++) {
                uint4 bv = Bc[((wn * 4 + j) * 4 + kk) * 32 + lane];
                uint32_t bl[2] = {bv.x, bv.y};
                uint32_t bh[2] = {bv.z, bv.w};
                mma_fp16(acc[0][2*j],     a0, bl);
                mma_fp16(acc[1][2*j],     a1, bl);
                mma_fp16(acc[0][2*j + 1], a0, bh);
                mma_fp16(acc[1][2*j + 1], a1, bh);
            }
        }
        cpa_wait<1>();
        __syncthreads();
    }

    // epilogue
    const int rowBase = mt * 128;
    const int colBase = nt * 128;
    #pragma unroll
    for (int mi = 0; mi < 2; mi++) {
        int r0 = rowBase + wm * 32 + mi * 16 + g;
        #pragma unroll
        for (int ni = 0; ni < 8; ni++) {
            int cc = colBase + wn * 64 + ni * 8 + 2 * t;
            if (!qkv_mode) {
                float* dst = Cf + (size_t)r0 * HH + cc;
                *reinterpret_cast<float2*>(dst)            = make_float2(acc[mi][ni][0], acc[mi][ni][1]);
                *reinterpret_cast<float2*>(dst + 8ull*HH)  = make_float2(acc[mi][ni][2], acc[mi][ni][3]);
            } else {
                int b2 = r0 >> 11, s = r0 & 2047;
                int h2 = cc >> 7, d = cc & 127;
                int c2 = d & 15;
                if (z == 0) {
                    int uix = (c2 & 8) ? 2 : 0;
                    int lanep = g * 4 + ((c2 & 7) >> 1);
                    size_t idx = ((size_t)((b2*NH + h2)*32 + (s >> 6))) * 4096
                               + (((s & 63) >> 4) * 8 + (d >> 4)) * 128 + lanep * 4;
                    Cq[idx + uix]     = pk2(acc[mi][ni][0], acc[mi][ni][1]);
                    Cq[idx + uix + 1] = pk2(acc[mi][ni][2], acc[mi][ni][3]);
                } else if (z == 1) {
                    int uix = (c2 & 8) ? 1 : 0;
                    int lanep = g * 4 + ((c2 & 7) >> 1);
                    size_t idx = ((size_t)((b2*NH + h2)*32 + (s >> 6))) * 4096
                               + (((s & 63) >> 4) * 8 + (d >> 4)) * 128 + lanep * 4;
                    Ck[idx + uix]     = pk2(acc[mi][ni][0], acc[mi][ni][1]);
                    Ck[idx + uix + 2] = pk2(acc[mi][ni][2], acc[mi][ni][3]);
                } else {
                    // V: n = d, k = s
                    __half* Vh = (__half*)Cv;
                    int n2 = d & 15, gn = n2 & 7, nu = n2 >> 3;
                    int tk = g >> 1, hf = g & 1;
                    size_t base = ((size_t)((b2*NH + h2)*32 + (s >> 6))) * 4096
                                + ((d >> 4) * 4 + ((s & 63) >> 4)) * 128;
                    size_t a0i = (base + (gn*4 + tk)     * 4 + nu*2) * 2 + hf;
                    size_t a1i = (base + (gn*4 + tk + 4) * 4 + nu*2) * 2 + hf;
                    Vh[a0i]     = __float2half_rn(acc[mi][ni][0]);
                    Vh[a1i]     = __float2half_rn(acc[mi][ni][1]);
                    Vh[a0i + 2] = __float2half_rn(acc[mi][ni][2]);
                    Vh[a1i + 2] = __float2half_rn(acc[mi][ni][3]);
                }
            }
        }
    }
}

// ============================================================================
// Flash attention (causal), fp16 mma m16n8k16, fragment-packed operands.
// Q tile 64, K/V tile 64 single-buffer with post-consume prefetch, P in
// A-pack smem. 128 threads (4 warps x 16 q-rows), 56KB smem -> 3 CTAs/SM.
// qt reversed (heaviest CTAs launch first) for tail balance.
// ============================================================================
#define AQ_U4 0
#define AK_U4 1024
#define AV_U4 2048
#define AP_U4 3072
#define ATTN_SMEM (3584 * 16)   // 57344 bytes

__global__ void __launch_bounds__(128, 3) attn_kernel()
{
    extern __shared__ uint4 smq[];
    uint4* Qs = smq + AQ_U4;
    uint4* Ks = smq + AK_U4;
    uint4* Vs = smq + AV_U4;
    uint4* Ps = smq + AP_U4;

    const int tid  = threadIdx.x;
    const int lane = tid & 31;
    const int warp = tid >> 5;        // 0..3
    const int g = lane >> 2, t = lane & 3;

    const int qt = 31 - blockIdx.x;   // reversed: big tiles first
    const int h  = blockIdx.y;
    const int b  = blockIdx.z;

    const int bh = b * NH + h;
    const uint4* Qg = reinterpret_cast<const uint4*>(g_q) + ((size_t)(bh * 32 + qt)) * 1024;
    const uint4* Kg = reinterpret_cast<const uint4*>(g_k) + ((size_t)bh * 32) * 1024;
    const uint4* Vg = reinterpret_cast<const uint4*>(g_v) + ((size_t)bh * 32) * 1024;

    const uint32_t sQ = (uint32_t)__cvta_generic_to_shared(Qs);
    const uint32_t sK = (uint32_t)__cvta_generic_to_shared(Ks);
    const uint32_t sV = (uint32_t)__cvta_generic_to_shared(Vs);

    // Q (group 1), K[0] (group 2), V[0] (group 3)
    #pragma unroll
    for (int i = 0; i < 8; i++) {
        int off = i * 128 + tid;
        cpa16(sQ + (uint32_t)off * 16u, Qg + off);
    }
    cpa_commit();
    #pragma unroll
    for (int i = 0; i < 8; i++) {
        int off = i * 128 + tid;
        cpa16(sK + (uint32_t)off * 16u, Kg + off);
    }
    cpa_commit();
    #pragma unroll
    for (int i = 0; i < 8; i++) {
        int off = i * 128 + tid;
        cpa16(sV + (uint32_t)off * 16u, Vg + off);
    }
    cpa_commit();

    float o[16][4];
    #pragma unroll
    for (int ni = 0; ni < 16; ni++)
        #pragma unroll
        for (int j = 0; j < 4; j++) o[ni][j] = 0.f;

    const float NEGINF = -1e30f;
    float mrow0 = NEGINF, mrow1 = NEGINF;
    float lrow0 = 0.f,    lrow1 = 0.f;
    const float sl = 0.088388347648318447f * 1.4426950408889634f;  // 1/sqrt(128)*log2e

    const int qrow = warp * 16 + g;
    const int nkt = qt + 1;

    #pragma unroll 1
    for (int kt = 0; kt < nkt; kt++) {
        // K[kt] ready (newest pending = V[kt])
        cpa_wait<1>();
        __syncthreads();

        // S = Q K^T : 8 k16-steps
        float s[8][4];
        #pragma unroll
        for (int ni = 0; ni < 8; ni++)
            #pragma unroll
            for (int j = 0; j < 4; j++) s[ni][j] = 0.f;

        #pragma unroll
        for (int kk = 0; kk < 8; kk++) {
            uint4 av = Qs[(warp * 8 + kk) * 32 + lane];
            uint32_t a[4] = {av.x, av.y, av.z, av.w};
            #pragma unroll
            for (int nb = 0; nb < 4; nb++) {
                uint4 bv = Ks[(nb * 8 + kk) * 32 + lane];
                uint32_t bl[2] = {bv.x, bv.y};
                uint32_t bh2[2] = {bv.z, bv.w};
                mma_fp16(s[2*nb],     a, bl);
                mma_fp16(s[2*nb + 1], a, bh2);
            }
        }

        // Ks consumed -> prefetch K[kt+1]
        __syncthreads();
        if (kt + 1 < nkt) {
            const uint4* Kt = Kg + (size_t)(kt + 1) * 1024;
            #pragma unroll
            for (int i = 0; i < 8; i++) {
                int off = i * 128 + tid;
                cpa16(sK + (uint32_t)off * 16u, Kt + off);
            }
        }
        cpa_commit();

        #pragma unroll
        for (int ni = 0; ni < 8; ni++)
            #pragma unroll
            for (int j = 0; j < 4; j++) s[ni][j] *= sl;

        // causal mask (diagonal tile only)
        if (kt == qt) {
            int q0 = qt * 64 + qrow;
            #pragma unroll
            for (int ni = 0; ni < 8; ni++) {
                int kg = kt * 64 + ni * 8 + 2 * t;
                if (kg     > q0)     s[ni][0] = NEGINF;
                if (kg + 1 > q0)     s[ni][1] = NEGINF;
                if (kg     > q0 + 8) s[ni][2] = NEGINF;
                if (kg + 1 > q0 + 8) s[ni][3] = NEGINF;
            }
        }

        // online softmax
        float mx0 = NEGINF, mx1 = NEGINF;
        #pragma unroll
        for (int ni = 0; ni < 8; ni++) {
            mx0 = fmaxf(mx0, fmaxf(s[ni][0], s[ni][1]));
            mx1 = fmaxf(mx1, fmaxf(s[ni][2], s[ni][3]));
        }
        mx0 = fmaxf(mx0, __shfl_xor_sync(0xffffffffu, mx0, 1));
        mx0 = fmaxf(mx0, __shfl_xor_sync(0xffffffffu, mx0, 2));
        mx1 = fmaxf(mx1, __shfl_xor_sync(0xffffffffu, mx1, 1));
        mx1 = fmaxf(mx1, __shfl_xor_sync(0xffffffffu, mx1, 2));

        float mn0 = fmaxf(mrow0, mx0), mn1 = fmaxf(mrow1, mx1);
        float al0 = exp2f(mrow0 - mn0), al1 = exp2f(mrow1 - mn1);
        mrow0 = mn0; mrow1 = mn1;

        float rs0 = 0.f, rs1 = 0.f;
        #pragma unroll
        for (int ni = 0; ni < 8; ni++) {
            s[ni][0] = exp2f(s[ni][0] - mn0); rs0 += s[ni][0];
            s[ni][1] = exp2f(s[ni][1] - mn0); rs0 += s[ni][1];
            s[ni][2] = exp2f(s[ni][2] - mn1); rs1 += s[ni][2];
            s[ni][3] = exp2f(s[ni][3] - mn1); rs1 += s[ni][3];
        }
        rs0 += __shfl_xor_sync(0xffffffffu, rs0, 1);
        rs0 += __shfl_xor_sync(0xffffffffu, rs0, 2);
        rs1 += __shfl_xor_sync(0xffffffffu, rs1, 1);
        rs1 += __shfl_xor_sync(0xffffffffu, rs1, 2);
        lrow0 = lrow0 * al0 + rs0;
        lrow1 = lrow1 * al1 + rs1;

        // skip accumulator rescale when the running max is unchanged warp-wide
        bool noscale = __all_sync(0xffffffffu, (al0 == 1.f) && (al1 == 1.f));
        if (!noscale) {
            #pragma unroll
            for (int ni = 0; ni < 16; ni++) {
                o[ni][0] *= al0; o[ni][1] *= al0;
                o[ni][2] *= al1; o[ni][3] *= al1;
            }
        }

        // V[kt] ready (newest pending = K[kt+1])
        cpa_wait<1>();
        __syncthreads();

        // write P (fp16) into A-pack smem; warp-private
        {
            uint32_t* Pu = reinterpret_cast<uint32_t*>(Ps);
            #pragma unroll
            for (int ni = 0; ni < 8; ni++) {
                int c  = ni * 8 + 2 * t;
                int k16 = c >> 4, c2 = c & 15;
                int uix = (c2 & 8) ? 2 : 0;
                int lanep = g * 4 + ((c2 & 7) >> 1);
                uint32_t idx = ((warp * 4 + k16) * 32 + lanep) * 4;
                Pu[idx + uix]     = pk2(s[ni][0], s[ni][1]);
                Pu[idx + uix + 1] = pk2(s[ni][2], s[ni][3]);
            }
        }
        __syncwarp();

        // O += P V : 4 k16-steps
        #pragma unroll
        for (int kc = 0; kc < 4; kc++) {
            uint4 av = Ps[(warp * 4 + kc) * 32 + lane];
            uint32_t a[4] = {av.x, av.y, av.z, av.w};
            #pragma unroll
            for (int j = 0; j < 8; j++) {
                uint4 bv = Vs[(j * 4 + kc) * 32 + lane];
                uint32_t bl[2] = {bv.x, bv.y};
                uint32_t bh2[2] = {bv.z, bv.w};
                mma_fp16(o[2*j],     a, bl);
                mma_fp16(o[2*j + 1], a, bh2);
            }
        }

        // Vs consumed -> prefetch V[kt+1]
        __syncthreads();
        if (kt + 1 < nkt) {
            const uint4* Vt = Vg + (size_t)(kt + 1) * 1024;
            #pragma unroll
            for (int i = 0; i < 8; i++) {
                int off = i * 128 + tid;
                cpa16(sV + (uint32_t)off * 16u, Vt + off);
            }
        }
        cpa_commit();
    }

    // normalize + store O into packed A layout (fp16) for the output GEMM
    {
        float i0 = 1.f / lrow0, i1 = 1.f / lrow1;
        const int m_tile = b * 16 + (qt >> 1);
        const int m16o = (qt & 1) * 4 + warp;
        #pragma unroll
        for (int ni = 0; ni < 16; ni++) {
            int dl = ni * 8 + 2 * t;
            int Kg2 = h * 128 + dl;
            int ks = Kg2 >> 6, k16 = (Kg2 >> 4) & 3, c2 = dl & 15;
            int uix = (c2 & 8) ? 2 : 0;
            int lanep = g * 4 + ((c2 & 7) >> 1);
            size_t idx = ((((size_t)m_tile * 32 + ks) * 8 + m16o) * 4 + k16) * 128 + lanep * 4;
            g_o[idx + uix]     = pk2(o[ni][0] * i0, o[ni][1] * i0);
            g_o[idx + uix + 1] = pk2(o[ni][2] * i1, o[ni][3] * i1);
        }
    }
}

// ============================================================================
extern "C" void kernel_launch(void* const* d_in, const int* in_sizes, int n_in,
                              void* d_out, int out_size) {
    const float* x  = (const float*)d_in[0];
    const float* wq = (const float*)d_in[1];
    const float* wk = (const float*)d_in[2];
    const float* wv = (const float*)d_in[3];
    const float* wo = (const float*)d_in[4];
    float* out = (float*)d_out;

    uint32_t *q, *k, *v, *o, *xr, *wr;
    cudaGetSymbolAddress((void**)&q,  g_q);
    cudaGetSymbolAddress((void**)&k,  g_k);
    cudaGetSymbolAddress((void**)&v,  g_v);
    cudaGetSymbolAddress((void**)&o,  g_o);
    cudaGetSymbolAddress((void**)&xr, g_x);
    cudaGetSymbolAddress((void**)&wr, g_w);

    cudaFuncSetAttribute(gemm_fp16_kernel, cudaFuncAttributeMaxDynamicSharedMemorySize, GEMM_SMEM);
    cudaFuncSetAttribute(attn_kernel,      cudaFuncAttributeMaxDynamicSharedMemorySize, ATTN_SMEM);

    // pack fp32 -> fp16 fragment layouts (smem-staged, coalesced)
    pack_a_kernel<<<dim3(MM / 128, 32), 256>>>(x, (uint4*)xr);
    pack_b_kernel<<<dim3(HH / 128, 32, 4), 256>>>(wq, wk, wv, wo, (uint4*)wr);

    dim3 gblk(256);

    // fused QKV (z selects weight + packed destination)
    gemm_fp16_kernel<<<dim3(HH / 128, MM / 128, 3), gblk, GEMM_SMEM>>>(
        (const uint4*)xr, (const uint4*)wr, q, k, v, nullptr, 1);

    attn_kernel<<<dim3(SS / 64, NH, BB), 128, ATTN_SMEM>>>();

    // output projection (A = packed g_o, W = packed wo)
    gemm_fp16_kernel<<<dim3(HH / 128, MM / 128, 1), gblk, GEMM_SMEM>>>(
        (const uint4*)o, (const uint4*)wr + 3ull * WSTRIDE_U4,
        nullptr, nullptr, nullptr, out, 0);
}